// round 15
// baseline (speedup 1.0000x reference)
#include <cuda_runtime.h>
#include <cuda_fp16.h>
#include <math.h>
#include <stdint.h>

#define DN    512
#define DQv   256
#define NPG   4096
#define NB    64
#define MI    8
#define NTOT  (NB*NPG)
#define KSEL  1229           // ceil(0.3 * 4096)

#define BM   128
#define BN   64              // quarter of DQv; 4 col-blocks per row slab
#define BK   32
#define NSTG (DN/BK)         // 16

// ---------------- scratch ----------------
__device__ float  g_s4[4][NB * MI * NPG];  // partial scores per col-quarter (32 MB)
__device__ __half g_Whi[DN * DQv];         // W*512 split hi
__device__ __half g_Wlo[DN * DQv];         // W*512 split lo

// ---------------- smem layout (bytes) ----------------
#define A_PAD  40     // halves per A row (32 data + 8 pad) -> 80B (5x16, odd)
#define B_PADB 72     // halves per B row (64 data + 8 pad) -> 144B (9x16, odd)
#define A_STG  10240  // 128 x 80B
#define B_STG  4608   // 32 x 144B
#define SM_AHI 0                      // 2 x 10240
#define SM_ALO 20480                  // 2 x 10240
#define SM_BHI 40960                  // 2 x 4608
#define SM_BLO 50176                  // 2 x 4608
#define SM_US  59392                  // 8*64 floats = 2048
#define SM_BNv 61440                  // 64 floats = 256
#define SM_DYN 61696

__device__ __forceinline__ uint32_t smem_u32(const void* p) {
    uint32_t a;
    asm("{ .reg .u64 t; cvta.to.shared.u64 t, %1; cvt.u32.u64 %0, t; }"
        : "=r"(a) : "l"(p));
    return a;
}

#define LDSM4(r, addr) \
    asm volatile("ldmatrix.sync.aligned.m8n8.x4.shared.b16 {%0,%1,%2,%3}, [%4];" \
        : "=r"((r)[0]), "=r"((r)[1]), "=r"((r)[2]), "=r"((r)[3]) : "r"(addr))

#define LDSM4T(r, addr) \
    asm volatile("ldmatrix.sync.aligned.m8n8.x4.trans.shared.b16 {%0,%1,%2,%3}, [%4];" \
        : "=r"((r)[0]), "=r"((r)[1]), "=r"((r)[2]), "=r"((r)[3]) : "r"(addr))

#define MMA16816(c, a, b0, b1) \
    asm volatile("mma.sync.aligned.m16n8k16.row.col.f32.f16.f16.f32 " \
        "{%0,%1,%2,%3}, {%4,%5,%6,%7}, {%8,%9}, {%0,%1,%2,%3};" \
        : "+f"((c)[0]), "+f"((c)[1]), "+f"((c)[2]), "+f"((c)[3]) \
        : "r"((a)[0]), "r"((a)[1]), "r"((a)[2]), "r"((a)[3]), "r"(b0), "r"(b1))

#define CPASYNC16(dst, src) \
    asm volatile("cp.async.ca.shared.global [%0], [%1], 16;" \
        :: "r"(dst), "l"(src) : "memory")
#define CPASYNC_COMMIT() asm volatile("cp.async.commit_group;" ::: "memory")
#define CPASYNC_WAIT0()  asm volatile("cp.async.wait_group 0;" ::: "memory")

// ---------------------------------------------------------------------------
// Prologue: W [512][256] fp32 -> fp16 Dekker split of W*512 (exact residual)
// ---------------------------------------------------------------------------
__global__ void convert_w(const float* __restrict__ Wn) {
    int idx = blockIdx.x * 256 + threadIdx.x;     // 0..131071
    float w = Wn[idx] * 512.0f;
    __half hi = __float2half_rn(w);
    __half lo = __float2half_rn(w - __half2float(hi));
    g_Whi[idx] = hi;
    g_Wlo[idx] = lo;
}

// ---------------------------------------------------------------------------
// Main: h = gelu((x@Wn)+bn) fused with partial scores over this block's 64
// cols. fp16 2-split, 3-term HMMA, fp32 accum. grid = (2048, 4).
// BN=64 -> acc halves to 32 regs -> 2 CTAs/SM (tail overlap across CTAs).
// ---------------------------------------------------------------------------
__global__ void __launch_bounds__(256, 2)
gemm_hmma(const float* __restrict__ x, const float* __restrict__ u,
          const float* __restrict__ bn)
{
    extern __shared__ char smem[];
    const uint32_t sb = smem_u32(smem);
    const int tid  = threadIdx.x;
    const int wid  = tid >> 5, lane = tid & 31;
    const int wm   = wid & 3, wn = wid >> 2;     // warp grid 4(M) x 2(N)
    const int rowBase = blockIdx.x * BM;
    const int colBase = blockIdx.y * BN;
    const int b = rowBase >> 12;
    float* gs = g_s4[blockIdx.y];

    // stage Us (8 x 64 cols of this quarter) and bn
    float* UsS = (float*)(smem + SM_US);
    float* bnS = (float*)(smem + SM_BNv);
    for (int i = tid; i < MI * BN; i += 256) {
        int m = i >> 6, c = i & 63;
        UsS[i] = u[(m * NB + b) * DQv + colBase + c];
    }
    if (tid < BN) bnS[tid] = bn[colBase + tid];

    // ---- loaders
    const int arow = tid >> 1;                 // 128 rows, 2 thr/row
    const int ac0  = (tid & 1) * 16;           // 16 k's each
    const float* Ap = x + (size_t)(rowBase + arow) * DN + ac0;
    const int aoff  = (arow * A_PAD + ac0) * 2;

    const int brow = tid >> 3;                 // 32 k-rows, 8 thr/row
    const int bc0  = (tid & 7) * 8;            // 8 cols (16B) each
    const __half* WHp = g_Whi + (size_t)brow * DQv + colBase + bc0;
    const __half* WLp = g_Wlo + (size_t)brow * DQv + colBase + bc0;
    const int boff  = (brow * B_PADB + bc0) * 2;

    // ldmatrix per-lane base terms
    const uint32_t aHiB = sb + SM_AHI, aLoB = sb + SM_ALO;
    const uint32_t bHiB = sb + SM_BHI, bLoB = sb + SM_BLO;
    const uint32_t arow_l = ((wm * 32 + (lane & 15)) * A_PAD + (lane >> 4) * 8) * 2;
    const uint32_t brow_l = ((lane & 15) * B_PADB + wn * 32 + (lane >> 4) * 8) * 2;

    float acc[2][4][4];     // 32 regs (half of BN=128 version)
    #pragma unroll
    for (int mt = 0; mt < 2; ++mt)
        #pragma unroll
        for (int nt = 0; nt < 4; ++nt)
            #pragma unroll
            for (int i = 0; i < 4; ++i) acc[mt][nt][i] = 0.f;

    float4 fA[4];

    auto issueB = [&](int s, int kt) {
        const __half* ph = WHp + (size_t)kt * BK * DQv;
        const __half* pl = WLp + (size_t)kt * BK * DQv;
        CPASYNC16(bHiB + s * B_STG + boff, ph);
        CPASYNC16(bLoB + s * B_STG + boff, pl);
        CPASYNC_COMMIT();
    };

    auto storeA = [&](int s) {
        const float* vf = (const float*)fA;
        uint4 hi[2], lo[2];
        uint32_t* hw = (uint32_t*)hi;
        uint32_t* lw = (uint32_t*)lo;
        #pragma unroll
        for (int q = 0; q < 8; ++q) {
            uint32_t hp[2], lp[2];
            #pragma unroll
            for (int e = 0; e < 2; ++e) {
                float w = vf[2 * q + e] * 64.0f;
                __half h = __float2half_rn(w);
                float r = w - __half2float(h);
                __half l = __float2half_rn(r);
                hp[e] = __half_as_ushort(h);
                lp[e] = __half_as_ushort(l);
            }
            hw[q] = hp[0] | (hp[1] << 16);
            lw[q] = lp[0] | (lp[1] << 16);
        }
        char* aH = smem + SM_AHI + s * A_STG + aoff;
        char* aL = smem + SM_ALO + s * A_STG + aoff;
        *(uint4*)(aH)      = hi[0];
        *(uint4*)(aH + 16) = hi[1];
        *(uint4*)(aL)      = lo[0];
        *(uint4*)(aL + 16) = lo[1];
    };

    // ---- prologue: stage 0
    issueB(0, 0);
    {
        const float4* p = (const float4*)Ap;
        fA[0] = p[0]; fA[1] = p[1]; fA[2] = p[2]; fA[3] = p[3];
    }
    storeA(0);
    CPASYNC_WAIT0();
    __syncthreads();

    for (int kt = 0; kt < NSTG; ++kt) {
        const int cur = kt & 1;

        if (kt + 1 < NSTG) {
            issueB(cur ^ 1, kt + 1);
            const float4* p = (const float4*)(Ap + (kt + 1) * BK);
            fA[0] = p[0]; fA[1] = p[1]; fA[2] = p[2]; fA[3] = p[3];
        }

        // compute: 2 x k16 steps
        #pragma unroll
        for (int kk = 0; kk < 2; ++kk) {
            uint32_t ah[2][4], al[2][4];
            #pragma unroll
            for (int mt = 0; mt < 2; ++mt) {
                uint32_t off = arow_l + (uint32_t)((mt * 16 * A_PAD + kk * 16) * 2);
                LDSM4(ah[mt], aHiB + cur * A_STG + off);
                LDSM4(al[mt], aLoB + cur * A_STG + off);
            }
            #pragma unroll
            for (int np = 0; np < 2; ++np) {
                uint32_t off = brow_l + (uint32_t)((kk * 16 * B_PADB + np * 16) * 2);
                uint32_t bh[4], bl[4];
                LDSM4T(bh, bHiB + cur * B_STG + off);
                LDSM4T(bl, bLoB + cur * B_STG + off);
                #pragma unroll
                for (int mt = 0; mt < 2; ++mt) {
                    #pragma unroll
                    for (int st = 0; st < 2; ++st) {
                        float* c = acc[mt][np * 2 + st];
                        MMA16816(c, ah[mt], bh[2 * st], bh[2 * st + 1]);
                        MMA16816(c, ah[mt], bl[2 * st], bl[2 * st + 1]);
                        MMA16816(c, al[mt], bh[2 * st], bh[2 * st + 1]);
                    }
                }
            }
        }

        if (kt + 1 < NSTG) storeA(cur ^ 1);
        CPASYNC_WAIT0();
        __syncthreads();
    }

    // ---- epilogue: scale back, bias, exact GELU, partial score dots
    const float inv = 1.0f / 32768.0f;     // undo x*64 * W*512
    float p[4][8];
    #pragma unroll
    for (int r = 0; r < 4; ++r)
        #pragma unroll
        for (int m = 0; m < MI; ++m) p[r][m] = 0.f;

    #pragma unroll
    for (int mt = 0; mt < 2; ++mt) {
        #pragma unroll
        for (int nt = 0; nt < 4; ++nt) {
            #pragma unroll
            for (int i = 0; i < 4; ++i) {
                const int col = wn * 32 + nt * 8 + (lane & 3) * 2 + (i & 1);
                float v = acc[mt][nt][i] * inv + bnS[col];
                float g = 0.5f * v * (1.0f + erff(v * 0.70710678118654752f));
                const int r = mt * 2 + (i >> 1);
                #pragma unroll
                for (int m = 0; m < MI; ++m)
                    p[r][m] = fmaf(g, UsS[m * BN + col], p[r][m]);
            }
        }
    }

    // reduce across the 4 lanes of each quad (cols partition)
    #pragma unroll
    for (int off = 1; off <= 2; off <<= 1)
        #pragma unroll
        for (int r = 0; r < 4; ++r)
            #pragma unroll
            for (int m = 0; m < MI; ++m)
                p[r][m] += __shfl_xor_sync(0xffffffffu, p[r][m], off);

    // combine the two wn halves via smem (reuse A region; all reads done)
    float* ps = (float*)(smem + SM_AHI);   // [2][128][8] floats = 8 KB
    if ((lane & 3) == 0) {
        #pragma unroll
        for (int r = 0; r < 4; ++r) {
            const int row = wm * 32 + (r >> 1) * 16 + (lane >> 2) + (r & 1) * 8;
            #pragma unroll
            for (int m = 0; m < MI; ++m)
                ps[(wn * 128 + row) * MI + m] = p[r][m];
        }
    }
    __syncthreads();

    for (int e = tid; e < BM * MI; e += 256) {
        const int row = e >> 3, m = e & 7;
        const int node = (rowBase & (NPG - 1)) + row;
        gs[(b * MI + m) * NPG + node] = ps[row * MI + m] + ps[(128 + row) * MI + m];
    }
}

// ---------------------------------------------------------------------------
// Kernel 2: per graph — softmax, gate, EXACT K-th largest via 4-pass radix
// select on float bits (monotone for positive floats), mask = gate >= kth.
// Deterministic: histogram counts are order-independent.
// ---------------------------------------------------------------------------
__global__ void __launch_bounds__(1024)
gate_topk(float* __restrict__ out)
{
    __shared__ float gate[NPG];        // 16 KB
    __shared__ unsigned hist[256];
    __shared__ float red_a[32];
    __shared__ float red_b[32];
    __shared__ unsigned sh_sel, sh_rank;

    const int b = blockIdx.x;
    const int tid = threadIdx.x;
    const int lane = tid & 31, wid = tid >> 5;

    for (int i = tid; i < NPG; i += 1024) gate[i] = 0.f;

    for (int m = 0; m < MI; ++m) {
        const size_t base = (size_t)(b * MI + m) * NPG;
        float v[4];
        float mx = -3.4e38f;
        #pragma unroll
        for (int i = 0; i < 4; ++i) {
            const int idx = (i << 10) + tid;
            v[i] = g_s4[0][base + idx] + g_s4[1][base + idx]
                 + g_s4[2][base + idx] + g_s4[3][base + idx];
            mx = fmaxf(mx, v[i]);
        }
        #pragma unroll
        for (int off = 16; off > 0; off >>= 1)
            mx = fmaxf(mx, __shfl_xor_sync(0xffffffffu, mx, off));
        if (lane == 0) red_a[wid] = mx;
        __syncthreads();
        mx = red_a[0];
        #pragma unroll
        for (int i = 1; i < 32; ++i) mx = fmaxf(mx, red_a[i]);

        float e[4], se = 0.f;
        #pragma unroll
        for (int i = 0; i < 4; ++i) { e[i] = expf(v[i] - mx); se += e[i]; }
        #pragma unroll
        for (int off = 16; off > 0; off >>= 1)
            se += __shfl_xor_sync(0xffffffffu, se, off);
        if (lane == 0) red_b[wid] = se;
        __syncthreads();
        float tot = 0.f;
        #pragma unroll
        for (int i = 0; i < 32; ++i) tot += red_b[i];

        #pragma unroll
        for (int i = 0; i < 4; ++i)
            gate[(i << 10) + tid] += e[i] / tot;   // per-thread-private slots
        __syncthreads();
    }

    // ---- radix select: exact bit pattern of K-th largest gate value.
    unsigned rank = KSEL;
    unsigned prefix = 0;
    #pragma unroll 1
    for (int d = 24; d >= 0; d -= 8) {
        for (int i = tid; i < 256; i += 1024) hist[i] = 0u;
        __syncthreads();
        #pragma unroll
        for (int i = 0; i < 4; ++i) {
            unsigned key = __float_as_uint(gate[(i << 10) + tid]);
            bool match = (d == 24) || ((key >> (d + 8)) == (prefix >> (d + 8)));
            if (match) atomicAdd(&hist[(key >> d) & 255], 1u);
        }
        __syncthreads();
        if (tid == 0) {
            unsigned c = 0;
            unsigned bb = 255;
            for (;; --bb) {
                c += hist[bb];
                if (c >= rank || bb == 0) break;
            }
            sh_sel  = bb;
            sh_rank = rank - (c - hist[bb]);
        }
        __syncthreads();
        prefix |= (sh_sel << d);
        rank = sh_rank;
        __syncthreads();
    }

    const float kth = __uint_as_float(prefix);   // exact K-th largest
    float* o = out + b * NPG;
    for (int i = tid; i < NPG; i += 1024)
        o[i] = (gate[i] >= kth) ? 1.0f : 0.0f;
}

// ---------------------------------------------------------------------------
extern "C" void kernel_launch(void* const* d_in, const int* in_sizes, int n_in,
                              void* d_out, int out_size) {
    const float* x  = (const float*)d_in[0];
    const float* u  = (const float*)d_in[1];
    const float* Wn = (const float*)d_in[2];
    const float* bn = (const float*)d_in[3];
    // d_in[4] = batch (equal sorted segments -> implicit), d_in[5] = edge_index (unused)

    cudaFuncSetAttribute(gemm_hmma,
                         cudaFuncAttributeMaxDynamicSharedMemorySize, SM_DYN);

    convert_w<<<DN * DQv / 256, 256>>>(Wn);
    dim3 grid(NTOT / BM, 4);
    gemm_hmma<<<grid, 256, SM_DYN>>>(x, u, bn);
    gate_topk<<<NB, 1024>>>((float*)d_out);
}

// round 16
// speedup vs baseline: 1.0682x; 1.0682x over previous
#include <cuda_runtime.h>
#include <cuda_fp16.h>
#include <math.h>
#include <stdint.h>

#define DN    512
#define DQv   256
#define NPG   4096
#define NB    64
#define MI    8
#define NTOT  (NB*NPG)
#define KSEL  1229           // ceil(0.3 * 4096)

#define BM   128
#define BN   128
#define BK   32
#define NSTG (DN/BK)         // 16

// ---------------- scratch ----------------
__device__ float g_s0[NB * MI * NPG];     // scores partial, col-half 0 (8 MB)
__device__ float g_s1[NB * MI * NPG];     // col-half 1
__device__ __half g_Whi[DN * DQv];        // W*512 split hi
__device__ __half g_Wlo[DN * DQv];        // W*512 split lo

// ---------------- smem layout (bytes) ----------------
#define A_PAD 40      // halves per A row (32 data + 8 pad)
#define B_PAD 136     // halves per B row (128 data + 8 pad)
#define SM_AHI 0                      // [2][128*40] halves = 20480 B
#define SM_ALO 20480
#define SM_BHI 40960                  // [2][32*136] halves = 17408 B
#define SM_BLO 58368
#define SM_US  75776                  // UsT[128][8] floats = 4096 B
#define SM_BNv 79872                  // 128 floats = 512 B
#define SM_DYN 80384
#define A_STG  10240                  // bytes per A stage
#define B_STG  8704                   // bytes per B stage

__device__ __forceinline__ uint32_t smem_u32(const void* p) {
    uint32_t a;
    asm("{ .reg .u64 t; cvta.to.shared.u64 t, %1; cvt.u32.u64 %0, t; }"
        : "=r"(a) : "l"(p));
    return a;
}

__device__ __forceinline__ unsigned long long fma2(unsigned long long a,
                                                   unsigned long long b,
                                                   unsigned long long c) {
    unsigned long long d;
    asm("fma.rn.f32x2 %0, %1, %2, %3;" : "=l"(d) : "l"(a), "l"(b), "l"(c));
    return d;
}

#define LDSM4(r, addr) \
    asm volatile("ldmatrix.sync.aligned.m8n8.x4.shared.b16 {%0,%1,%2,%3}, [%4];" \
        : "=r"((r)[0]), "=r"((r)[1]), "=r"((r)[2]), "=r"((r)[3]) : "r"(addr))

#define LDSM4T(r, addr) \
    asm volatile("ldmatrix.sync.aligned.m8n8.x4.trans.shared.b16 {%0,%1,%2,%3}, [%4];" \
        : "=r"((r)[0]), "=r"((r)[1]), "=r"((r)[2]), "=r"((r)[3]) : "r"(addr))

#define MMA16816(c, a, b0, b1) \
    asm volatile("mma.sync.aligned.m16n8k16.row.col.f32.f16.f16.f32 " \
        "{%0,%1,%2,%3}, {%4,%5,%6,%7}, {%8,%9}, {%0,%1,%2,%3};" \
        : "+f"((c)[0]), "+f"((c)[1]), "+f"((c)[2]), "+f"((c)[3]) \
        : "r"((a)[0]), "r"((a)[1]), "r"((a)[2]), "r"((a)[3]), "r"(b0), "r"(b1))

#define CPASYNC16(dst, src) \
    asm volatile("cp.async.ca.shared.global [%0], [%1], 16;" \
        :: "r"(dst), "l"(src) : "memory")
#define CPASYNC_COMMIT() asm volatile("cp.async.commit_group;" ::: "memory")
#define CPASYNC_WAIT0()  asm volatile("cp.async.wait_group 0;" ::: "memory")

// ---------------------------------------------------------------------------
// Prologue: W [512][256] fp32 -> fp16 Dekker split of W*512 (exact residual)
// ---------------------------------------------------------------------------
__global__ void convert_w(const float* __restrict__ Wn) {
    int idx = blockIdx.x * 256 + threadIdx.x;     // 0..131071
    float w = Wn[idx] * 512.0f;
    __half hi = __float2half_rn(w);
    __half lo = __float2half_rn(w - __half2float(hi));
    g_Whi[idx] = hi;
    g_Wlo[idx] = lo;
}

// ---------------------------------------------------------------------------
// Main: h = gelu((x@Wn)+bn) fused with partial scores over this block's 128
// cols. fp16 2-split, 3-term HMMA, fp32 accum. grid = (2048, 2).
// Epilogue uses transposed U + packed f32x2 FMAs.
// ---------------------------------------------------------------------------
__global__ void __launch_bounds__(256)
gemm_hmma(const float* __restrict__ x, const float* __restrict__ u,
          const float* __restrict__ bn)
{
    extern __shared__ char smem[];
    const uint32_t sb = smem_u32(smem);
    const int tid  = threadIdx.x;
    const int wid  = tid >> 5, lane = tid & 31;
    const int wm   = wid & 3, wn = wid >> 2;     // warp grid 4(M) x 2(N)
    const int rowBase = blockIdx.x * BM;
    const int colBase = blockIdx.y * BN;
    const int b = rowBase >> 12;
    float* gs = blockIdx.y ? g_s1 : g_s0;

    // stage U TRANSPOSED: UsT[c][m] (c = col within this 128-half, m = 0..7)
    float* UsT = (float*)(smem + SM_US);
    float* bnS = (float*)(smem + SM_BNv);
    for (int i = tid; i < MI * BN; i += 256) {
        int m = i >> 7, c = i & 127;
        UsT[c * MI + m] = u[(m * NB + b) * DQv + colBase + c];
    }
    if (tid < BN) bnS[tid] = bn[colBase + tid];

    // ---- loaders
    const int arow = tid >> 1;                 // 128 rows, 2 thr/row
    const int ac0  = (tid & 1) * 16;           // 16 k's each
    const float* Ap = x + (size_t)(rowBase + arow) * DN + ac0;
    const int aoff  = (arow * A_PAD + ac0) * 2;

    const int brow = tid >> 3;                 // 32 k-rows, 8 thr/row
    const int bc0  = (tid & 7) * 16;           // 16 cols each
    const __half* WHp = g_Whi + (size_t)brow * DQv + colBase + bc0;
    const __half* WLp = g_Wlo + (size_t)brow * DQv + colBase + bc0;
    const int boff  = (brow * B_PAD + bc0) * 2;

    // ldmatrix per-lane base terms
    const uint32_t aHiB = sb + SM_AHI, aLoB = sb + SM_ALO;
    const uint32_t bHiB = sb + SM_BHI, bLoB = sb + SM_BLO;
    const uint32_t arow_l = ((wm * 32 + (lane & 15)) * A_PAD + (lane >> 4) * 8) * 2;
    const uint32_t brow_l = ((lane & 15) * B_PAD + wn * 64 + (lane >> 4) * 8) * 2;

    float acc[2][8][4];
    #pragma unroll
    for (int mt = 0; mt < 2; ++mt)
        #pragma unroll
        for (int nt = 0; nt < 8; ++nt)
            #pragma unroll
            for (int i = 0; i < 4; ++i) acc[mt][nt][i] = 0.f;

    float4 fA[4];

    auto issueB = [&](int s, int kt) {
        const __half* ph = WHp + (size_t)kt * BK * DQv;
        const __half* pl = WLp + (size_t)kt * BK * DQv;
        uint32_t dH = bHiB + s * B_STG + boff;
        uint32_t dL = bLoB + s * B_STG + boff;
        CPASYNC16(dH,      ph);
        CPASYNC16(dH + 16, ph + 8);
        CPASYNC16(dL,      pl);
        CPASYNC16(dL + 16, pl + 8);
        CPASYNC_COMMIT();
    };

    auto storeA = [&](int s) {
        const float* vf = (const float*)fA;
        uint4 hi[2], lo[2];
        uint32_t* hw = (uint32_t*)hi;
        uint32_t* lw = (uint32_t*)lo;
        #pragma unroll
        for (int q = 0; q < 8; ++q) {
            uint32_t hp[2], lp[2];
            #pragma unroll
            for (int e = 0; e < 2; ++e) {
                float w = vf[2 * q + e] * 64.0f;
                __half h = __float2half_rn(w);
                float r = w - __half2float(h);
                __half l = __float2half_rn(r);
                hp[e] = __half_as_ushort(h);
                lp[e] = __half_as_ushort(l);
            }
            hw[q] = hp[0] | (hp[1] << 16);
            lw[q] = lp[0] | (lp[1] << 16);
        }
        char* aH = smem + SM_AHI + s * A_STG + aoff;
        char* aL = smem + SM_ALO + s * A_STG + aoff;
        *(uint4*)(aH)      = hi[0];
        *(uint4*)(aH + 16) = hi[1];
        *(uint4*)(aL)      = lo[0];
        *(uint4*)(aL + 16) = lo[1];
    };

    // ---- prologue: stage 0
    issueB(0, 0);
    {
        const float4* p = (const float4*)Ap;
        fA[0] = p[0]; fA[1] = p[1]; fA[2] = p[2]; fA[3] = p[3];
    }
    storeA(0);
    CPASYNC_WAIT0();
    __syncthreads();

    for (int kt = 0; kt < NSTG; ++kt) {
        const int cur = kt & 1;

        if (kt + 1 < NSTG) {
            issueB(cur ^ 1, kt + 1);
            const float4* p = (const float4*)(Ap + (kt + 1) * BK);
            fA[0] = p[0]; fA[1] = p[1]; fA[2] = p[2]; fA[3] = p[3];
        }

        // compute: 2 x k16 steps
        #pragma unroll
        for (int kk = 0; kk < 2; ++kk) {
            uint32_t ah[2][4], al[2][4];
            #pragma unroll
            for (int mt = 0; mt < 2; ++mt) {
                uint32_t off = arow_l + (uint32_t)((mt * 16 * A_PAD + kk * 16) * 2);
                LDSM4(ah[mt], aHiB + cur * A_STG + off);
                LDSM4(al[mt], aLoB + cur * A_STG + off);
            }
            #pragma unroll
            for (int np = 0; np < 4; ++np) {
                uint32_t off = brow_l + (uint32_t)((kk * 16 * B_PAD + np * 16) * 2);
                uint32_t bh[4], bl[4];
                LDSM4T(bh, bHiB + cur * B_STG + off);
                LDSM4T(bl, bLoB + cur * B_STG + off);
                #pragma unroll
                for (int mt = 0; mt < 2; ++mt) {
                    #pragma unroll
                    for (int st = 0; st < 2; ++st) {
                        float* c = acc[mt][np * 2 + st];
                        MMA16816(c, ah[mt], bh[2 * st], bh[2 * st + 1]);
                        MMA16816(c, ah[mt], bl[2 * st], bl[2 * st + 1]);
                        MMA16816(c, al[mt], bh[2 * st], bh[2 * st + 1]);
                    }
                }
            }
        }

        if (kt + 1 < NSTG) storeA(cur ^ 1);
        CPASYNC_WAIT0();
        __syncthreads();
    }

    // ---- epilogue: scale back, bias, exact GELU, packed f32x2 score dots
    const float inv = 1.0f / 32768.0f;     // undo x*64 * W*512
    unsigned long long pp[4][4];           // p[r][m] packed as 4 f32x2 per r
    #pragma unroll
    for (int r = 0; r < 4; ++r)
        #pragma unroll
        for (int q = 0; q < 4; ++q) pp[r][q] = 0ULL;

    #pragma unroll
    for (int mt = 0; mt < 2; ++mt) {
        #pragma unroll
        for (int nt = 0; nt < 8; ++nt) {
            #pragma unroll
            for (int i = 0; i < 4; ++i) {
                const int col = wn * 64 + nt * 8 + (lane & 3) * 2 + (i & 1);
                float v = acc[mt][nt][i] * inv + bnS[col];
                float g = 0.5f * v * (1.0f + erff(v * 0.70710678118654752f));
                const int r = mt * 2 + (i >> 1);
                unsigned long long gg;
                asm("mov.b64 %0, {%1, %1};" : "=l"(gg) : "r"(__float_as_uint(g)));
                const ulonglong2 u0 = *(const ulonglong2*)&UsT[col * MI];
                const ulonglong2 u1 = *(const ulonglong2*)&UsT[col * MI + 4];
                pp[r][0] = fma2(gg, u0.x, pp[r][0]);
                pp[r][1] = fma2(gg, u0.y, pp[r][1]);
                pp[r][2] = fma2(gg, u1.x, pp[r][2]);
                pp[r][3] = fma2(gg, u1.y, pp[r][3]);
            }
        }
    }

    // unpack to scalars for the quad shuffle reduce
    float p[4][8];
    #pragma unroll
    for (int r = 0; r < 4; ++r)
        #pragma unroll
        for (int q = 0; q < 4; ++q) {
            p[r][2 * q]     = __uint_as_float((unsigned int)(pp[r][q]));
            p[r][2 * q + 1] = __uint_as_float((unsigned int)(pp[r][q] >> 32));
        }

    #pragma unroll
    for (int off = 1; off <= 2; off <<= 1)
        #pragma unroll
        for (int r = 0; r < 4; ++r)
            #pragma unroll
            for (int m = 0; m < MI; ++m)
                p[r][m] += __shfl_xor_sync(0xffffffffu, p[r][m], off);

    // combine the two wn halves via smem (reuse A region; all reads done)
    float* ps = (float*)(smem + SM_AHI);   // [2][128][8] floats = 8 KB
    if ((lane & 3) == 0) {
        #pragma unroll
        for (int r = 0; r < 4; ++r) {
            const int row = wm * 32 + (r >> 1) * 16 + (lane >> 2) + (r & 1) * 8;
            #pragma unroll
            for (int m = 0; m < MI; ++m)
                ps[(wn * 128 + row) * MI + m] = p[r][m];
        }
    }
    __syncthreads();

    for (int e = tid; e < BM * MI; e += 256) {
        const int row = e >> 3, m = e & 7;
        const int node = (rowBase & (NPG - 1)) + row;
        gs[(b * MI + m) * NPG + node] = ps[row * MI + m] + ps[(128 + row) * MI + m];
    }
}

// ---------------------------------------------------------------------------
// Kernel 2: per graph — softmax, gate, EXACT K-th largest via 4-pass radix
// select on float bits, mask = gate >= kth. (Round-13/14 validated.)
// ---------------------------------------------------------------------------
__global__ void __launch_bounds__(1024)
gate_topk(float* __restrict__ out)
{
    __shared__ float gate[NPG];        // 16 KB
    __shared__ unsigned hist[256];
    __shared__ float red_a[32];
    __shared__ float red_b[32];
    __shared__ unsigned sh_sel, sh_rank;

    const int b = blockIdx.x;
    const int tid = threadIdx.x;
    const int lane = tid & 31, wid = tid >> 5;

    for (int i = tid; i < NPG; i += 1024) gate[i] = 0.f;

    for (int m = 0; m < MI; ++m) {
        const float* s0 = g_s0 + (b * MI + m) * NPG;
        const float* s1 = g_s1 + (b * MI + m) * NPG;
        float v[4];
        float mx = -3.4e38f;
        #pragma unroll
        for (int i = 0; i < 4; ++i) {
            v[i] = s0[(i << 10) + tid] + s1[(i << 10) + tid];
            mx = fmaxf(mx, v[i]);
        }
        #pragma unroll
        for (int off = 16; off > 0; off >>= 1)
            mx = fmaxf(mx, __shfl_xor_sync(0xffffffffu, mx, off));
        if (lane == 0) red_a[wid] = mx;
        __syncthreads();
        mx = red_a[0];
        #pragma unroll
        for (int i = 1; i < 32; ++i) mx = fmaxf(mx, red_a[i]);

        float e[4], se = 0.f;
        #pragma unroll
        for (int i = 0; i < 4; ++i) { e[i] = expf(v[i] - mx); se += e[i]; }
        #pragma unroll
        for (int off = 16; off > 0; off >>= 1)
            se += __shfl_xor_sync(0xffffffffu, se, off);
        if (lane == 0) red_b[wid] = se;
        __syncthreads();
        float tot = 0.f;
        #pragma unroll
        for (int i = 0; i < 32; ++i) tot += red_b[i];

        #pragma unroll
        for (int i = 0; i < 4; ++i)
            gate[(i << 10) + tid] += e[i] / tot;   // per-thread-private slots
        __syncthreads();
    }

    // ---- radix select: exact bit pattern of K-th largest gate value.
    unsigned rank = KSEL;
    unsigned prefix = 0;
    #pragma unroll 1
    for (int d = 24; d >= 0; d -= 8) {
        for (int i = tid; i < 256; i += 1024) hist[i] = 0u;
        __syncthreads();
        #pragma unroll
        for (int i = 0; i < 4; ++i) {
            unsigned key = __float_as_uint(gate[(i << 10) + tid]);
            bool match = (d == 24) || ((key >> (d + 8)) == (prefix >> (d + 8)));
            if (match) atomicAdd(&hist[(key >> d) & 255], 1u);
        }
        __syncthreads();
        if (tid == 0) {
            unsigned c = 0;
            unsigned bb = 255;
            for (;; --bb) {
                c += hist[bb];
                if (c >= rank || bb == 0) break;
            }
            sh_sel  = bb;
            sh_rank = rank - (c - hist[bb]);
        }
        __syncthreads();
        prefix |= (sh_sel << d);
        rank = sh_rank;
        __syncthreads();
    }

    const float kth = __uint_as_float(prefix);   // exact K-th largest
    float* o = out + b * NPG;
    for (int i = tid; i < NPG; i += 1024)
        o[i] = (gate[i] >= kth) ? 1.0f : 0.0f;
}

// ---------------------------------------------------------------------------
extern "C" void kernel_launch(void* const* d_in, const int* in_sizes, int n_in,
                              void* d_out, int out_size) {
    const float* x  = (const float*)d_in[0];
    const float* u  = (const float*)d_in[1];
    const float* Wn = (const float*)d_in[2];
    const float* bn = (const float*)d_in[3];
    // d_in[4] = batch (equal sorted segments -> implicit), d_in[5] = edge_index (unused)

    cudaFuncSetAttribute(gemm_hmma,
                         cudaFuncAttributeMaxDynamicSharedMemorySize, SM_DYN);

    convert_w<<<DN * DQv / 256, 256>>>(Wn);
    dim3 grid(NTOT / BM, 2);
    gemm_hmma<<<grid, 256, SM_DYN>>>(x, u, bn);
    gate_topk<<<NB, 1024>>>((float*)d_out);
}

// round 17
// speedup vs baseline: 1.0861x; 1.0168x over previous
#include <cuda_runtime.h>
#include <cuda_fp16.h>
#include <math.h>
#include <stdint.h>

#define DN    512
#define DQv   256
#define NPG   4096
#define NB    64
#define MI    8
#define NTOT  (NB*NPG)
#define KSEL  1229           // ceil(0.3 * 4096)

#define BM   128
#define BN   128
#define BK   32
#define NSTG (DN/BK)         // 16

// ---------------- scratch ----------------
__device__ float g_s0[NB * MI * NPG];     // scores partial, col-half 0 (8 MB)
__device__ float g_s1[NB * MI * NPG];     // col-half 1
__device__ __half g_Whi[DN * DQv];        // W*512 split hi
__device__ __half g_Wlo[DN * DQv];        // W*512 split lo
__device__ float g_mx[NB * MI];           // per-(b,m) max
__device__ float g_isum[NB * MI];         // per-(b,m) 1/sum(exp)

// ---------------- smem layout (bytes) ----------------
#define A_PAD 40      // halves per A row (32 data + 8 pad)
#define B_PAD 136     // halves per B row (128 data + 8 pad)
#define SM_AHI 0                      // [2][128*40] halves = 20480 B
#define SM_ALO 20480
#define SM_BHI 40960                  // [2][32*136] halves = 17408 B
#define SM_BLO 58368
#define SM_US  75776                  // 8*128 floats = 4096 B
#define SM_BNv 79872                  // 128 floats = 512 B
#define SM_DYN 80384
#define A_STG  10240                  // bytes per A stage
#define B_STG  8704                   // bytes per B stage

__device__ __forceinline__ uint32_t smem_u32(const void* p) {
    uint32_t a;
    asm("{ .reg .u64 t; cvta.to.shared.u64 t, %1; cvt.u32.u64 %0, t; }"
        : "=r"(a) : "l"(p));
    return a;
}

#define LDSM4(r, addr) \
    asm volatile("ldmatrix.sync.aligned.m8n8.x4.shared.b16 {%0,%1,%2,%3}, [%4];" \
        : "=r"((r)[0]), "=r"((r)[1]), "=r"((r)[2]), "=r"((r)[3]) : "r"(addr))

#define LDSM4T(r, addr) \
    asm volatile("ldmatrix.sync.aligned.m8n8.x4.trans.shared.b16 {%0,%1,%2,%3}, [%4];" \
        : "=r"((r)[0]), "=r"((r)[1]), "=r"((r)[2]), "=r"((r)[3]) : "r"(addr))

#define MMA16816(c, a, b0, b1) \
    asm volatile("mma.sync.aligned.m16n8k16.row.col.f32.f16.f16.f32 " \
        "{%0,%1,%2,%3}, {%4,%5,%6,%7}, {%8,%9}, {%0,%1,%2,%3};" \
        : "+f"((c)[0]), "+f"((c)[1]), "+f"((c)[2]), "+f"((c)[3]) \
        : "r"((a)[0]), "r"((a)[1]), "r"((a)[2]), "r"((a)[3]), "r"(b0), "r"(b1))

#define CPASYNC16(dst, src) \
    asm volatile("cp.async.ca.shared.global [%0], [%1], 16;" \
        :: "r"(dst), "l"(src) : "memory")
#define CPASYNC_COMMIT() asm volatile("cp.async.commit_group;" ::: "memory")
#define CPASYNC_WAIT0()  asm volatile("cp.async.wait_group 0;" ::: "memory")

// ---------------------------------------------------------------------------
// Prologue: W [512][256] fp32 -> fp16 Dekker split of W*512 (exact residual)
// ---------------------------------------------------------------------------
__global__ void convert_w(const float* __restrict__ Wn) {
    int idx = blockIdx.x * 256 + threadIdx.x;     // 0..131071
    float w = Wn[idx] * 512.0f;
    __half hi = __float2half_rn(w);
    __half lo = __float2half_rn(w - __half2float(hi));
    g_Whi[idx] = hi;
    g_Wlo[idx] = lo;
}

// ---------------------------------------------------------------------------
// Main GEMM (round-10 champion, verbatim): h = gelu((x@Wn)+bn) fused with
// partial scores. fp16 2-split, 3-term HMMA, fp32 accum. grid = (2048, 2).
// ---------------------------------------------------------------------------
__global__ void __launch_bounds__(256)
gemm_hmma(const float* __restrict__ x, const float* __restrict__ u,
          const float* __restrict__ bn)
{
    extern __shared__ char smem[];
    const uint32_t sb = smem_u32(smem);
    const int tid  = threadIdx.x;
    const int wid  = tid >> 5, lane = tid & 31;
    const int wm   = wid & 3, wn = wid >> 2;     // warp grid 4(M) x 2(N)
    const int rowBase = blockIdx.x * BM;
    const int colBase = blockIdx.y * BN;
    const int b = rowBase >> 12;
    float* gs = blockIdx.y ? g_s1 : g_s0;

    float* UsS = (float*)(smem + SM_US);
    float* bnS = (float*)(smem + SM_BNv);
    for (int i = tid; i < MI * BN; i += 256) {
        int m = i >> 7, c = i & 127;
        UsS[i] = u[(m * NB + b) * DQv + colBase + c];
    }
    if (tid < BN) bnS[tid] = bn[colBase + tid];

    const int arow = tid >> 1;
    const int ac0  = (tid & 1) * 16;
    const float* Ap = x + (size_t)(rowBase + arow) * DN + ac0;
    const int aoff  = (arow * A_PAD + ac0) * 2;

    const int brow = tid >> 3;
    const int bc0  = (tid & 7) * 16;
    const __half* WHp = g_Whi + (size_t)brow * DQv + colBase + bc0;
    const __half* WLp = g_Wlo + (size_t)brow * DQv + colBase + bc0;
    const int boff  = (brow * B_PAD + bc0) * 2;

    const uint32_t aHiB = sb + SM_AHI, aLoB = sb + SM_ALO;
    const uint32_t bHiB = sb + SM_BHI, bLoB = sb + SM_BLO;
    const uint32_t arow_l = ((wm * 32 + (lane & 15)) * A_PAD + (lane >> 4) * 8) * 2;
    const uint32_t brow_l = ((lane & 15) * B_PAD + wn * 64 + (lane >> 4) * 8) * 2;

    float acc[2][8][4];
    #pragma unroll
    for (int mt = 0; mt < 2; ++mt)
        #pragma unroll
        for (int nt = 0; nt < 8; ++nt)
            #pragma unroll
            for (int i = 0; i < 4; ++i) acc[mt][nt][i] = 0.f;

    float4 fA[4];

    auto issueB = [&](int s, int kt) {
        const __half* ph = WHp + (size_t)kt * BK * DQv;
        const __half* pl = WLp + (size_t)kt * BK * DQv;
        uint32_t dH = bHiB + s * B_STG + boff;
        uint32_t dL = bLoB + s * B_STG + boff;
        CPASYNC16(dH,      ph);
        CPASYNC16(dH + 16, ph + 8);
        CPASYNC16(dL,      pl);
        CPASYNC16(dL + 16, pl + 8);
        CPASYNC_COMMIT();
    };

    auto storeA = [&](int s) {
        const float* vf = (const float*)fA;
        uint4 hi[2], lo[2];
        uint32_t* hw = (uint32_t*)hi;
        uint32_t* lw = (uint32_t*)lo;
        #pragma unroll
        for (int q = 0; q < 8; ++q) {
            uint32_t hp[2], lp[2];
            #pragma unroll
            for (int e = 0; e < 2; ++e) {
                float w = vf[2 * q + e] * 64.0f;
                __half h = __float2half_rn(w);
                float r = w - __half2float(h);
                __half l = __float2half_rn(r);
                hp[e] = __half_as_ushort(h);
                lp[e] = __half_as_ushort(l);
            }
            hw[q] = hp[0] | (hp[1] << 16);
            lw[q] = lp[0] | (lp[1] << 16);
        }
        char* aH = smem + SM_AHI + s * A_STG + aoff;
        char* aL = smem + SM_ALO + s * A_STG + aoff;
        *(uint4*)(aH)      = hi[0];
        *(uint4*)(aH + 16) = hi[1];
        *(uint4*)(aL)      = lo[0];
        *(uint4*)(aL + 16) = lo[1];
    };

    issueB(0, 0);
    {
        const float4* p = (const float4*)Ap;
        fA[0] = p[0]; fA[1] = p[1]; fA[2] = p[2]; fA[3] = p[3];
    }
    storeA(0);
    CPASYNC_WAIT0();
    __syncthreads();

    for (int kt = 0; kt < NSTG; ++kt) {
        const int cur = kt & 1;

        if (kt + 1 < NSTG) {
            issueB(cur ^ 1, kt + 1);
            const float4* p = (const float4*)(Ap + (kt + 1) * BK);
            fA[0] = p[0]; fA[1] = p[1]; fA[2] = p[2]; fA[3] = p[3];
        }

        #pragma unroll
        for (int kk = 0; kk < 2; ++kk) {
            uint32_t ah[2][4], al[2][4];
            #pragma unroll
            for (int mt = 0; mt < 2; ++mt) {
                uint32_t off = arow_l + (uint32_t)((mt * 16 * A_PAD + kk * 16) * 2);
                LDSM4(ah[mt], aHiB + cur * A_STG + off);
                LDSM4(al[mt], aLoB + cur * A_STG + off);
            }
            #pragma unroll
            for (int np = 0; np < 4; ++np) {
                uint32_t off = brow_l + (uint32_t)((kk * 16 * B_PAD + np * 16) * 2);
                uint32_t bh[4], bl[4];
                LDSM4T(bh, bHiB + cur * B_STG + off);
                LDSM4T(bl, bLoB + cur * B_STG + off);
                #pragma unroll
                for (int mt = 0; mt < 2; ++mt) {
                    #pragma unroll
                    for (int st = 0; st < 2; ++st) {
                        float* c = acc[mt][np * 2 + st];
                        MMA16816(c, ah[mt], bh[2 * st], bh[2 * st + 1]);
                        MMA16816(c, ah[mt], bl[2 * st], bl[2 * st + 1]);
                        MMA16816(c, al[mt], bh[2 * st], bh[2 * st + 1]);
                    }
                }
            }
        }

        if (kt + 1 < NSTG) storeA(cur ^ 1);
        CPASYNC_WAIT0();
        __syncthreads();
    }

    const float inv = 1.0f / 32768.0f;
    float p[4][8];
    #pragma unroll
    for (int r = 0; r < 4; ++r)
        #pragma unroll
        for (int m = 0; m < MI; ++m) p[r][m] = 0.f;

    #pragma unroll
    for (int mt = 0; mt < 2; ++mt) {
        #pragma unroll
        for (int nt = 0; nt < 8; ++nt) {
            #pragma unroll
            for (int i = 0; i < 4; ++i) {
                const int col = wn * 64 + nt * 8 + (lane & 3) * 2 + (i & 1);
                float v = acc[mt][nt][i] * inv + bnS[col];
                float g = 0.5f * v * (1.0f + erff(v * 0.70710678118654752f));
                const int r = mt * 2 + (i >> 1);
                #pragma unroll
                for (int m = 0; m < MI; ++m)
                    p[r][m] = fmaf(g, UsS[m * BN + col], p[r][m]);
            }
        }
    }

    #pragma unroll
    for (int off = 1; off <= 2; off <<= 1)
        #pragma unroll
        for (int r = 0; r < 4; ++r)
            #pragma unroll
            for (int m = 0; m < MI; ++m)
                p[r][m] += __shfl_xor_sync(0xffffffffu, p[r][m], off);

    float* ps = (float*)(smem + SM_AHI);   // [2][128][8]
    if ((lane & 3) == 0) {
        #pragma unroll
        for (int r = 0; r < 4; ++r) {
            const int row = wm * 32 + (r >> 1) * 16 + (lane >> 2) + (r & 1) * 8;
            #pragma unroll
            for (int m = 0; m < MI; ++m)
                ps[(wn * 128 + row) * MI + m] = p[r][m];
        }
    }
    __syncthreads();

    for (int e = tid; e < BM * MI; e += 256) {
        const int row = e >> 3, m = e & 7;
        const int node = (rowBase & (NPG - 1)) + row;
        gs[(b * MI + m) * NPG + node] = ps[row * MI + m] + ps[(128 + row) * MI + m];
    }
}

// ---------------------------------------------------------------------------
// Kernel 2a: per (b,m) — max and 1/sum(exp) over 4096 nodes.
// 512 blocks (3.5x SM coverage) x 512 threads. Deterministic reductions.
// ---------------------------------------------------------------------------
__global__ void __launch_bounds__(512)
score_stats()
{
    __shared__ float vs[NPG];     // 16 KB: v = s0 + s1 staged once
    __shared__ float red[16];

    const int bm = blockIdx.x;                 // 0..511 = b*MI + m
    const int tid = threadIdx.x;
    const int lane = tid & 31, wid = tid >> 5;
    const float* s0 = g_s0 + (size_t)bm * NPG;
    const float* s1 = g_s1 + (size_t)bm * NPG;

    float mx = -3.4e38f;
    float v[8];
    #pragma unroll
    for (int i = 0; i < 8; ++i) {
        const int idx = (i << 9) + tid;
        v[i] = s0[idx] + s1[idx];
        vs[idx] = v[i];
        mx = fmaxf(mx, v[i]);
    }
    #pragma unroll
    for (int off = 16; off > 0; off >>= 1)
        mx = fmaxf(mx, __shfl_xor_sync(0xffffffffu, mx, off));
    if (lane == 0) red[wid] = mx;
    __syncthreads();
    mx = red[0];
    #pragma unroll
    for (int i = 1; i < 16; ++i) mx = fmaxf(mx, red[i]);

    float se = 0.f;
    #pragma unroll
    for (int i = 0; i < 8; ++i) se += expf(v[i] - mx);
    #pragma unroll
    for (int off = 16; off > 0; off >>= 1)
        se += __shfl_xor_sync(0xffffffffu, se, off);
    __syncthreads();              // red[] reuse
    if (lane == 0) red[wid] = se;
    __syncthreads();
    if (tid == 0) {
        float tot = 0.f;
        #pragma unroll
        for (int i = 0; i < 16; ++i) tot += red[i];
        g_mx[bm]   = mx;
        g_isum[bm] = 1.0f / tot;
    }
    (void)vs;   // staged for L2 warmth of the next kernel
}

// ---------------------------------------------------------------------------
// Kernel 2b: per graph — gate accumulation (barrier-free streaming; stats
// precomputed), EXACT K-th largest via 4-pass radix select, mask.
// ---------------------------------------------------------------------------
__global__ void __launch_bounds__(1024)
gate_mask(float* __restrict__ out)
{
    __shared__ float gate[NPG];        // 16 KB
    __shared__ unsigned hist[256];
    __shared__ unsigned sh_sel, sh_rank;

    const int b = blockIdx.x;
    const int tid = threadIdx.x;

    float acc[4] = {0.f, 0.f, 0.f, 0.f};
    #pragma unroll
    for (int m = 0; m < MI; ++m) {
        const size_t base = (size_t)(b * MI + m) * NPG;
        const float mx = g_mx[b * MI + m];
        const float is = g_isum[b * MI + m];
        #pragma unroll
        for (int i = 0; i < 4; ++i) {
            const int idx = (i << 10) + tid;
            float v = g_s0[base + idx] + g_s1[base + idx];
            acc[i] += expf(v - mx) * is;
        }
    }
    #pragma unroll
    for (int i = 0; i < 4; ++i) gate[(i << 10) + tid] = acc[i];
    __syncthreads();

    // ---- radix select: exact bit pattern of K-th largest gate value.
    // gates are > 0, so uint bit order == float order.
    unsigned rank = KSEL;
    unsigned prefix = 0;
    #pragma unroll 1
    for (int d = 24; d >= 0; d -= 8) {
        for (int i = tid; i < 256; i += 1024) hist[i] = 0u;
        __syncthreads();
        #pragma unroll
        for (int i = 0; i < 4; ++i) {
            unsigned key = __float_as_uint(gate[(i << 10) + tid]);
            bool match = (d == 24) || ((key >> (d + 8)) == (prefix >> (d + 8)));
            if (match) atomicAdd(&hist[(key >> d) & 255], 1u);
        }
        __syncthreads();
        if (tid == 0) {
            unsigned c = 0;
            unsigned bb = 255;
            for (;; --bb) {
                c += hist[bb];
                if (c >= rank || bb == 0) break;
            }
            sh_sel  = bb;
            sh_rank = rank - (c - hist[bb]);
        }
        __syncthreads();
        prefix |= (sh_sel << d);
        rank = sh_rank;
        __syncthreads();
    }

    const float kth = __uint_as_float(prefix);   // exact K-th largest
    float* o = out + b * NPG;
    for (int i = tid; i < NPG; i += 1024)
        o[i] = (gate[i] >= kth) ? 1.0f : 0.0f;
}

// ---------------------------------------------------------------------------
extern "C" void kernel_launch(void* const* d_in, const int* in_sizes, int n_in,
                              void* d_out, int out_size) {
    const float* x  = (const float*)d_in[0];
    const float* u  = (const float*)d_in[1];
    const float* Wn = (const float*)d_in[2];
    const float* bn = (const float*)d_in[3];
    // d_in[4] = batch (equal sorted segments -> implicit), d_in[5] = edge_index (unused)

    cudaFuncSetAttribute(gemm_hmma,
                         cudaFuncAttributeMaxDynamicSharedMemorySize, SM_DYN);

    convert_w<<<DN * DQv / 256, 256>>>(Wn);
    dim3 grid(NTOT / BM, 2);
    gemm_hmma<<<grid, 256, SM_DYN>>>(x, u, bn);
    score_stats<<<NB * MI, 512>>>();
    gate_mask<<<NB, 1024>>>((float*)d_out);
}